// round 1
// baseline (speedup 1.0000x reference)
#include <cuda_runtime.h>
#include <cstdint>

// Problem dims
#define BB 128      // batch
#define TT 1024     // seq
#define EE 512      // embed
#define HH 1024     // hidden
#define VV 512      // vocab

#define NB 128      // persistent blocks (<= 148 SMs, guaranteed co-resident)
#define NT 256      // threads per block

// ---------------- persistent device scratch (no allocations allowed) ----------------
__device__ __align__(16) float g_tokproj[VV * HH];                  // 2 MB: b_h0 + w_xh0 @ emb[v]
__device__ __align__(16) float g_part0[2][4][BB * HH];              // GEMM-A K-split partials (parity x 4)
__device__ __align__(16) float g_part1[2][4][BB * HH];              // GEMM-B K-split partials
__device__ __align__(16) float g_h0[BB * HH];                       // compact h0_t
__device__ __align__(16) float g_h1[BB * HH];                       // compact h1_{t-1}
__device__ __align__(16) float g_h1all[(size_t)TT * BB * HH];       // 512 MB: all h1 states for logits GEMM
__device__ unsigned long long g_arrive;                             // barrier arrival counter (monotonic)
__device__ unsigned long long g_epoch[NB];                          // per-block persistent epoch (replay-safe)

// ---------------- grid-wide barrier (software, replay-safe) ----------------
__device__ __forceinline__ void grid_bar(unsigned long long& epoch) {
    __syncthreads();
    if (threadIdx.x == 0) {
        __threadfence();
        atomicAdd(&g_arrive, 1ULL);
        epoch += (unsigned long long)NB;
        while (*(volatile unsigned long long*)&g_arrive < epoch) {
            __nanosleep(128);
        }
        __threadfence();
    }
    __syncthreads();
}

// ---------------- generic 64x64 tile GEMM: C[64,64] += sum_k A[m,k]*B[n,k] ----------------
// smem layout: s[k][r] with row stride 68 floats (conflict-light, float4-aligned reads)
template <typename LA, typename LB, typename ST>
__device__ __forceinline__ void gemm64(float* sA, float* sB, int kbeg, int kend,
                                       LA la, LB lb, ST st) {
    const int tid = threadIdx.x;
    const int tx = tid & 15;
    const int ty = tid >> 4;
    float acc[4][4];
#pragma unroll
    for (int i = 0; i < 4; i++)
#pragma unroll
        for (int j = 0; j < 4; j++) acc[i][j] = 0.f;

    for (int k0 = kbeg; k0 < kend; k0 += 32) {
        // stage 64x32 A-tile and B-tile, transposed to [k][r]
#pragma unroll
        for (int i = 0; i < 8; i++) {
            int idx = tid + i * NT;      // 0..2047
            int k = idx & 31;
            int r = idx >> 5;            // 0..63
            sA[k * 68 + r] = la(r, k0 + k);
            sB[k * 68 + r] = lb(r, k0 + k);
        }
        __syncthreads();
#pragma unroll
        for (int kk = 0; kk < 32; kk++) {
            float4 a = *(const float4*)(sA + kk * 68 + 4 * ty);
            float4 b = *(const float4*)(sB + kk * 68 + 4 * tx);
            float av[4] = {a.x, a.y, a.z, a.w};
            float bv[4] = {b.x, b.y, b.z, b.w};
#pragma unroll
            for (int i = 0; i < 4; i++)
#pragma unroll
                for (int j = 0; j < 4; j++)
                    acc[i][j] = fmaf(av[i], bv[j], acc[i][j]);
        }
        __syncthreads();
    }
#pragma unroll
    for (int i = 0; i < 4; i++) {
        float4 v = make_float4(acc[i][0], acc[i][1], acc[i][2], acc[i][3]);
        st(4 * ty + i, 4 * tx, v);
    }
}

// ---------------- the persistent RNN kernel ----------------
__global__ void __launch_bounds__(NT, 1) rnn_persistent_kernel(
    const int*   __restrict__ ids,     // [B,T]
    const float* __restrict__ emb,     // [V,E]
    const float* __restrict__ w_xh0,   // [H,E]
    const float* __restrict__ w_hh0,   // [H,H]
    const float* __restrict__ b_h0,    // [H]
    const float* __restrict__ w_xh1,   // [H,H]
    const float* __restrict__ w_hh1,   // [H,H]
    const float* __restrict__ b_h1,    // [H]
    const float* __restrict__ w_hy,    // [V,H]
    const float* __restrict__ b_y,     // [V]
    float* __restrict__ out,
    long long out_size)
{
    __shared__ float sA[32 * 68];
    __shared__ float sB[32 * 68];
    const int bid = blockIdx.x;
    const int tid = threadIdx.x;

    unsigned long long epoch = 0;
    if (tid == 0) epoch = g_epoch[bid];

    // ================= prologue =================
    // zero part0[parity 0] (needed at t=0) and g_h1 (h1_{-1} = 0)
    {
        float* z = &g_part0[0][0][0];   // 4 * B*H floats
        for (int i = tid; i < 4096; i += NT) z[bid * 4096 + i] = 0.f;
        for (int i = tid; i < 1024; i += NT) g_h1[bid * 1024 + i] = 0.f;
    }
    // tokproj[v][h] = b_h0[h] + sum_e emb[v][e] * w_xh0[h][e]
    {
        int mt = bid & 7;            // 8 m-tiles over V=512
        int nt = bid >> 3;           // 16 n-tiles over H=1024
        int m0 = mt * 64, n0 = nt * 64;
        gemm64(sA, sB, 0, EE,
            [&](int r, int k) { return emb[(m0 + r) * EE + k]; },
            [&](int r, int k) { return w_xh0[(n0 + r) * EE + k]; },
            [&](int m, int n, float4 v) {
                int col = n0 + n;
                float4 bb = *(const float4*)(b_h0 + col);
                v.x += bb.x; v.y += bb.y; v.z += bb.z; v.w += bb.w;
                *(float4*)(g_tokproj + (size_t)(m0 + m) * HH + col) = v;
            });
    }
    grid_bar(epoch);

    // ================= sequential loop =================
    for (int t = 0; t < TT; t++) {
        const int p = t & 1;
        const int q = p ^ 1;

        // ---- phase 1: GEMM A (pre0 partials) + finalize h1_{t-1} ----
        if (t > 0) {
            int mt = bid & 1;
            int nt = (bid >> 1) & 15;
            int kc = bid >> 5;
            int m0 = mt * 64, n0 = nt * 64;
            gemm64(sA, sB, kc * 256, kc * 256 + 256,
                [&](int r, int k) { return g_h0[(m0 + r) * HH + k]; },
                [&](int r, int k) { return w_hh0[(n0 + r) * HH + k]; },
                [&](int m, int n, float4 v) {
                    *(float4*)&g_part0[p][kc][(m0 + m) * HH + n0 + n] = v;
                });
            // h1_{t-1} = tanh(b_h1 + sum partials)  -> g_h1 (compact) + g_h1all[t-1]
            for (int i = tid; i < 1024; i += NT) {
                int idx = bid * 1024 + i;
                int k = idx & (HH - 1);
                float s = b_h1[k] + g_part1[q][0][idx] + g_part1[q][1][idx]
                                  + g_part1[q][2][idx] + g_part1[q][3][idx];
                float v = tanhf(s);
                g_h1[idx] = v;
                g_h1all[(size_t)(t - 1) * (BB * HH) + idx] = v;
            }
        }
        grid_bar(epoch);

        // ---- phase 2: GEMM B (pre1 partials) + finalize h0_t compact ----
        {
            int mt = bid & 1;
            int nt = (bid >> 1) & 15;
            int kc = bid >> 5;
            int m0 = mt * 64, n0 = nt * 64;
            int kbeg = kc * 512;
            auto stp = [&](int m, int n, float4 v) {
                *(float4*)&g_part1[p][kc][(m0 + m) * HH + n0 + n] = v;
            };
            if (kc < 2) {
                // first K-half: A = h0_t = tanh(tokproj[id] + sum part0[p])
                gemm64(sA, sB, kbeg, kbeg + 512,
                    [&](int r, int k) {
                        int b = m0 + r;
                        int id = ids[b * TT + t];
                        float s = g_tokproj[(size_t)id * HH + k]
                                + g_part0[p][0][b * HH + k] + g_part0[p][1][b * HH + k]
                                + g_part0[p][2][b * HH + k] + g_part0[p][3][b * HH + k];
                        return tanhf(s);
                    },
                    [&](int r, int k) { return w_xh1[(n0 + r) * HH + k]; },
                    stp);
            } else {
                // second K-half: A = h1_{t-1} (compact)
                gemm64(sA, sB, kbeg - 1024, kbeg - 1024 + 512,
                    [&](int r, int k) { return g_h1[(m0 + r) * HH + k]; },
                    [&](int r, int k) { return w_hh1[(n0 + r) * HH + k]; },
                    stp);
            }
            // compact h0_t for next step's GEMM A
            for (int i = tid; i < 1024; i += NT) {
                int idx = bid * 1024 + i;
                int b = idx >> 10;
                int k = idx & (HH - 1);
                int id = ids[b * TT + t];
                float s = g_tokproj[(size_t)id * HH + k]
                        + g_part0[p][0][idx] + g_part0[p][1][idx]
                        + g_part0[p][2][idx] + g_part0[p][3][idx];
                g_h0[idx] = tanhf(s);
            }
        }
        grid_bar(epoch);
    }

    // ================= epilogue =================
    // finalize h1_{T-1} (p=1 at t=1023), write final states if requested
    {
        const long long full = (long long)BB * TT * VV + 2LL * BB * HH;
        for (int i = tid; i < 1024; i += NT) {
            int idx = bid * 1024 + i;
            int k = idx & (HH - 1);
            float s = b_h1[k] + g_part1[1][0][idx] + g_part1[1][1][idx]
                              + g_part1[1][2][idx] + g_part1[1][3][idx];
            float v = tanhf(s);
            g_h1all[(size_t)(TT - 1) * (BB * HH) + idx] = v;
            if (out_size >= full) {
                out[(size_t)BB * TT * VV + idx] = g_h0[idx];            // h0 final
                out[(size_t)BB * TT * VV + BB * HH + idx] = v;           // h1 final
            }
        }
    }
    grid_bar(epoch);
    if (tid == 0) g_epoch[bid] = epoch;   // persist epoch for next replay

    // logits = h1all @ w_hy^T + b_y   (parallel GEMM, 16384 tiles of 64x64)
    for (int tile = bid; tile < 16384; tile += NB) {
        int mt = tile >> 3;            // 2048 m-tiles over B*T rows (layout [t][b])
        int nt = tile & 7;             // 8 n-tiles over V=512
        int m0 = mt * 64, n0 = nt * 64;
        gemm64(sA, sB, 0, HH,
            [&](int r, int k) { return g_h1all[(size_t)(m0 + r) * HH + k]; },
            [&](int r, int k) { return w_hy[(n0 + r) * HH + k]; },
            [&](int m, int n, float4 v) {
                int row = m0 + m;
                int tt = row >> 7;       // t
                int b  = row & 127;      // batch
                int col = n0 + n;
                float4 bb = *(const float4*)(b_y + col);
                v.x += bb.x; v.y += bb.y; v.z += bb.z; v.w += bb.w;
                *(float4*)&out[((size_t)b * TT + tt) * VV + col] = v;
            });
    }
}

// ---------------- launch ----------------
extern "C" void kernel_launch(void* const* d_in, const int* in_sizes, int n_in,
                              void* d_out, int out_size) {
    const int*   ids   = (const int*)d_in[0];
    const float* emb   = (const float*)d_in[1];
    const float* w_xh0 = (const float*)d_in[2];
    const float* w_hh0 = (const float*)d_in[3];
    const float* b_h0  = (const float*)d_in[4];
    const float* w_xh1 = (const float*)d_in[5];
    const float* w_hh1 = (const float*)d_in[6];
    const float* b_h1  = (const float*)d_in[7];
    const float* w_hy  = (const float*)d_in[8];
    const float* b_y   = (const float*)d_in[9];
    float* out = (float*)d_out;

    rnn_persistent_kernel<<<NB, NT>>>(ids, emb, w_xh0, w_hh0, b_h0,
                                      w_xh1, w_hh1, b_h1, w_hy, b_y,
                                      out, (long long)out_size);
}

// round 2
// speedup vs baseline: 1.0099x; 1.0099x over previous
#include <cuda_runtime.h>
#include <cstdint>

// Problem dims
#define BB 128      // batch
#define TT 1024     // seq
#define EE 512      // embed
#define HH 1024     // hidden
#define VV 512      // vocab

#define NB 128      // persistent blocks (<= 148 SMs, guaranteed co-resident)
#define NT 256      // threads per block

// ---------------- persistent device scratch (no allocations allowed) ----------------
__device__ __align__(16) float g_tokproj[VV * HH];                  // 2 MB: b_h0 + w_xh0 @ emb[v]
__device__ __align__(16) float g_part0[2][4][BB * HH];              // GEMM-A K-split partials (parity x 4)
__device__ __align__(16) float g_part1[2][4][BB * HH];              // GEMM-B K-split partials
__device__ __align__(16) float g_h0[BB * HH];                       // compact h0_t
__device__ __align__(16) float g_h1[BB * HH];                       // compact h1_{t-1}
__device__ __align__(16) float g_h1all[(size_t)TT * BB * HH];       // 512 MB: all h1 states for logits GEMM
__device__ unsigned long long g_arrive;                             // barrier arrival counter (monotonic)
__device__ unsigned long long g_epoch[NB];                          // per-block persistent epoch (replay-safe)

// ---------------- grid-wide barrier (software, replay-safe) ----------------
__device__ __forceinline__ void grid_bar(unsigned long long& epoch) {
    __syncthreads();
    if (threadIdx.x == 0) {
        __threadfence();
        atomicAdd(&g_arrive, 1ULL);
        epoch += (unsigned long long)NB;
        while (*(volatile unsigned long long*)&g_arrive < epoch) {
            __nanosleep(128);
        }
        __threadfence();
    }
    __syncthreads();
}

// ---------------- generic 64x64 tile GEMM: C[64,64] += sum_k A[m,k]*B[n,k] ----------------
// smem layout: s[k][r] with row stride 68 floats (conflict-light, float4-aligned reads)
template <typename LA, typename LB, typename ST>
__device__ __forceinline__ void gemm64(float* sA, float* sB, int kbeg, int kend,
                                       LA la, LB lb, ST st) {
    const int tid = threadIdx.x;
    const int tx = tid & 15;
    const int ty = tid >> 4;
    float acc[4][4];
#pragma unroll
    for (int i = 0; i < 4; i++)
#pragma unroll
        for (int j = 0; j < 4; j++) acc[i][j] = 0.f;

    for (int k0 = kbeg; k0 < kend; k0 += 32) {
        // stage 64x32 A-tile and B-tile, transposed to [k][r]
#pragma unroll
        for (int i = 0; i < 8; i++) {
            int idx = tid + i * NT;      // 0..2047
            int k = idx & 31;
            int r = idx >> 5;            // 0..63
            sA[k * 68 + r] = la(r, k0 + k);
            sB[k * 68 + r] = lb(r, k0 + k);
        }
        __syncthreads();
#pragma unroll
        for (int kk = 0; kk < 32; kk++) {
            float4 a = *(const float4*)(sA + kk * 68 + 4 * ty);
            float4 b = *(const float4*)(sB + kk * 68 + 4 * tx);
            float av[4] = {a.x, a.y, a.z, a.w};
            float bv[4] = {b.x, b.y, b.z, b.w};
#pragma unroll
            for (int i = 0; i < 4; i++)
#pragma unroll
                for (int j = 0; j < 4; j++)
                    acc[i][j] = fmaf(av[i], bv[j], acc[i][j]);
        }
        __syncthreads();
    }
#pragma unroll
    for (int i = 0; i < 4; i++) {
        float4 v = make_float4(acc[i][0], acc[i][1], acc[i][2], acc[i][3]);
        st(4 * ty + i, 4 * tx, v);
    }
}

// ---------------- the persistent RNN kernel ----------------
__global__ void __launch_bounds__(NT, 1) rnn_persistent_kernel(
    const int*   __restrict__ ids,     // [B,T]
    const float* __restrict__ emb,     // [V,E]
    const float* __restrict__ w_xh0,   // [H,E]
    const float* __restrict__ w_hh0,   // [H,H]
    const float* __restrict__ b_h0,    // [H]
    const float* __restrict__ w_xh1,   // [H,H]
    const float* __restrict__ w_hh1,   // [H,H]
    const float* __restrict__ b_h1,    // [H]
    const float* __restrict__ w_hy,    // [V,H]
    const float* __restrict__ b_y,     // [V]
    float* __restrict__ out,
    long long out_size)
{
    __shared__ float sA[32 * 68];
    __shared__ float sB[32 * 68];
    const int bid = blockIdx.x;
    const int tid = threadIdx.x;

    unsigned long long epoch = 0;
    if (tid == 0) epoch = g_epoch[bid];

    // ================= prologue =================
    // zero part0[parity 0] (needed at t=0) and g_h1 (h1_{-1} = 0)
    {
        float* z = &g_part0[0][0][0];   // 4 * B*H floats
        for (int i = tid; i < 4096; i += NT) z[bid * 4096 + i] = 0.f;
        for (int i = tid; i < 1024; i += NT) g_h1[bid * 1024 + i] = 0.f;
    }
    // tokproj[v][h] = b_h0[h] + sum_e emb[v][e] * w_xh0[h][e]
    {
        int mt = bid & 7;            // 8 m-tiles over V=512
        int nt = bid >> 3;           // 16 n-tiles over H=1024
        int m0 = mt * 64, n0 = nt * 64;
        gemm64(sA, sB, 0, EE,
            [&](int r, int k) { return emb[(m0 + r) * EE + k]; },
            [&](int r, int k) { return w_xh0[(n0 + r) * EE + k]; },
            [&](int m, int n, float4 v) {
                int col = n0 + n;
                float4 bb = *(const float4*)(b_h0 + col);
                v.x += bb.x; v.y += bb.y; v.z += bb.z; v.w += bb.w;
                *(float4*)(g_tokproj + (size_t)(m0 + m) * HH + col) = v;
            });
    }
    grid_bar(epoch);

    // ================= sequential loop =================
    for (int t = 0; t < TT; t++) {
        const int p = t & 1;
        const int q = p ^ 1;

        // ---- phase 1: GEMM A (pre0 partials) + finalize h1_{t-1} ----
        if (t > 0) {
            int mt = bid & 1;
            int nt = (bid >> 1) & 15;
            int kc = bid >> 5;
            int m0 = mt * 64, n0 = nt * 64;
            gemm64(sA, sB, kc * 256, kc * 256 + 256,
                [&](int r, int k) { return g_h0[(m0 + r) * HH + k]; },
                [&](int r, int k) { return w_hh0[(n0 + r) * HH + k]; },
                [&](int m, int n, float4 v) {
                    *(float4*)&g_part0[p][kc][(m0 + m) * HH + n0 + n] = v;
                });
            // h1_{t-1} = tanh(b_h1 + sum partials)  -> g_h1 (compact) + g_h1all[t-1]
            for (int i = tid; i < 1024; i += NT) {
                int idx = bid * 1024 + i;
                int k = idx & (HH - 1);
                float s = b_h1[k] + g_part1[q][0][idx] + g_part1[q][1][idx]
                                  + g_part1[q][2][idx] + g_part1[q][3][idx];
                float v = tanhf(s);
                g_h1[idx] = v;
                g_h1all[(size_t)(t - 1) * (BB * HH) + idx] = v;
            }
        }
        grid_bar(epoch);

        // ---- phase 2: GEMM B (pre1 partials) + finalize h0_t compact ----
        {
            int mt = bid & 1;
            int nt = (bid >> 1) & 15;
            int kc = bid >> 5;
            int m0 = mt * 64, n0 = nt * 64;
            int kbeg = kc * 512;
            auto stp = [&](int m, int n, float4 v) {
                *(float4*)&g_part1[p][kc][(m0 + m) * HH + n0 + n] = v;
            };
            if (kc < 2) {
                // first K-half: A = h0_t = tanh(tokproj[id] + sum part0[p])
                gemm64(sA, sB, kbeg, kbeg + 512,
                    [&](int r, int k) {
                        int b = m0 + r;
                        int id = ids[b * TT + t];
                        float s = g_tokproj[(size_t)id * HH + k]
                                + g_part0[p][0][b * HH + k] + g_part0[p][1][b * HH + k]
                                + g_part0[p][2][b * HH + k] + g_part0[p][3][b * HH + k];
                        return tanhf(s);
                    },
                    [&](int r, int k) { return w_xh1[(n0 + r) * HH + k]; },
                    stp);
            } else {
                // second K-half: A = h1_{t-1} (compact)
                gemm64(sA, sB, kbeg - 1024, kbeg - 1024 + 512,
                    [&](int r, int k) { return g_h1[(m0 + r) * HH + k]; },
                    [&](int r, int k) { return w_hh1[(n0 + r) * HH + k]; },
                    stp);
            }
            // compact h0_t for next step's GEMM A
            for (int i = tid; i < 1024; i += NT) {
                int idx = bid * 1024 + i;
                int b = idx >> 10;
                int k = idx & (HH - 1);
                int id = ids[b * TT + t];
                float s = g_tokproj[(size_t)id * HH + k]
                        + g_part0[p][0][idx] + g_part0[p][1][idx]
                        + g_part0[p][2][idx] + g_part0[p][3][idx];
                g_h0[idx] = tanhf(s);
            }
        }
        grid_bar(epoch);
    }

    // ================= epilogue =================
    // finalize h1_{T-1} (p=1 at t=1023), write final states if requested
    {
        const long long full = (long long)BB * TT * VV + 2LL * BB * HH;
        for (int i = tid; i < 1024; i += NT) {
            int idx = bid * 1024 + i;
            int k = idx & (HH - 1);
            float s = b_h1[k] + g_part1[1][0][idx] + g_part1[1][1][idx]
                              + g_part1[1][2][idx] + g_part1[1][3][idx];
            float v = tanhf(s);
            g_h1all[(size_t)(TT - 1) * (BB * HH) + idx] = v;
            if (out_size >= full) {
                out[(size_t)BB * TT * VV + idx] = g_h0[idx];            // h0 final
                out[(size_t)BB * TT * VV + BB * HH + idx] = v;           // h1 final
            }
        }
    }
    grid_bar(epoch);
    if (tid == 0) g_epoch[bid] = epoch;   // persist epoch for next replay

    // logits = h1all @ w_hy^T + b_y   (parallel GEMM, 16384 tiles of 64x64)
    for (int tile = bid; tile < 16384; tile += NB) {
        int mt = tile >> 3;            // 2048 m-tiles over B*T rows (layout [t][b])
        int nt = tile & 7;             // 8 n-tiles over V=512
        int m0 = mt * 64, n0 = nt * 64;
        gemm64(sA, sB, 0, HH,
            [&](int r, int k) { return g_h1all[(size_t)(m0 + r) * HH + k]; },
            [&](int r, int k) { return w_hy[(n0 + r) * HH + k]; },
            [&](int m, int n, float4 v) {
                int row = m0 + m;
                int tt = row >> 7;       // t
                int b  = row & 127;      // batch
                int col = n0 + n;
                float4 bb = *(const float4*)(b_y + col);
                v.x += bb.x; v.y += bb.y; v.z += bb.z; v.w += bb.w;
                *(float4*)&out[((size_t)b * TT + tt) * VV + col] = v;
            });
    }
}

// ---------------- launch ----------------
extern "C" void kernel_launch(void* const* d_in, const int* in_sizes, int n_in,
                              void* d_out, int out_size) {
    const int*   ids   = (const int*)d_in[0];
    const float* emb   = (const float*)d_in[1];
    const float* w_xh0 = (const float*)d_in[2];
    const float* w_hh0 = (const float*)d_in[3];
    const float* b_h0  = (const float*)d_in[4];
    const float* w_xh1 = (const float*)d_in[5];
    const float* w_hh1 = (const float*)d_in[6];
    const float* b_h1  = (const float*)d_in[7];
    const float* w_hy  = (const float*)d_in[8];
    const float* b_y   = (const float*)d_in[9];
    float* out = (float*)d_out;

    rnn_persistent_kernel<<<NB, NT>>>(ids, emb, w_xh0, w_hh0, b_h0,
                                      w_xh1, w_hh1, b_h1, w_hy, b_y,
                                      out, (long long)out_size);
}

// round 3
// speedup vs baseline: 1.0135x; 1.0036x over previous
#include <cuda_runtime.h>
#include <cstdint>

// Problem dims
#define BB 128      // batch
#define TT 1024     // seq
#define EE 512      // embed
#define HH 1024     // hidden
#define VV 512      // vocab

#define NB 128      // persistent blocks (<= 148 SMs, guaranteed co-resident)
#define NT 256      // threads per block

// ---------------- persistent device scratch (no allocations allowed) ----------------
__device__ __align__(16) float g_tokproj[VV * HH];                  // 2 MB: b_h0 + w_xh0 @ emb[v]
__device__ __align__(16) float g_part0[2][4][BB * HH];              // GEMM-A K-split partials (parity x 4)
__device__ __align__(16) float g_part1[2][4][BB * HH];              // GEMM-B K-split partials
__device__ __align__(16) float g_h0[BB * HH];                       // compact h0_t
__device__ __align__(16) float g_h1[BB * HH];                       // compact h1_{t-1}
__device__ __align__(16) float g_h1all[(size_t)TT * BB * HH];       // 512 MB: all h1 states for logits GEMM
__device__ unsigned long long g_arrive;                             // barrier arrival counter (monotonic)
__device__ unsigned long long g_epoch[NB];                          // per-block persistent epoch (replay-safe)

// ---------------- grid-wide barrier (software, replay-safe) ----------------
__device__ __forceinline__ void grid_bar(unsigned long long& epoch) {
    __syncthreads();
    if (threadIdx.x == 0) {
        __threadfence();
        atomicAdd(&g_arrive, 1ULL);
        epoch += (unsigned long long)NB;
        while (*(volatile unsigned long long*)&g_arrive < epoch) {
            __nanosleep(128);
        }
        __threadfence();
    }
    __syncthreads();
}

// ---------------- generic 64x64 tile GEMM: C[64,64] += sum_k A[m,k]*B[n,k] ----------------
// smem layout: s[k][r] with row stride 68 floats (conflict-light, float4-aligned reads)
template <typename LA, typename LB, typename ST>
__device__ __forceinline__ void gemm64(float* sA, float* sB, int kbeg, int kend,
                                       LA la, LB lb, ST st) {
    const int tid = threadIdx.x;
    const int tx = tid & 15;
    const int ty = tid >> 4;
    float acc[4][4];
#pragma unroll
    for (int i = 0; i < 4; i++)
#pragma unroll
        for (int j = 0; j < 4; j++) acc[i][j] = 0.f;

    for (int k0 = kbeg; k0 < kend; k0 += 32) {
        // stage 64x32 A-tile and B-tile, transposed to [k][r]
#pragma unroll
        for (int i = 0; i < 8; i++) {
            int idx = tid + i * NT;      // 0..2047
            int k = idx & 31;
            int r = idx >> 5;            // 0..63
            sA[k * 68 + r] = la(r, k0 + k);
            sB[k * 68 + r] = lb(r, k0 + k);
        }
        __syncthreads();
#pragma unroll
        for (int kk = 0; kk < 32; kk++) {
            float4 a = *(const float4*)(sA + kk * 68 + 4 * ty);
            float4 b = *(const float4*)(sB + kk * 68 + 4 * tx);
            float av[4] = {a.x, a.y, a.z, a.w};
            float bv[4] = {b.x, b.y, b.z, b.w};
#pragma unroll
            for (int i = 0; i < 4; i++)
#pragma unroll
                for (int j = 0; j < 4; j++)
                    acc[i][j] = fmaf(av[i], bv[j], acc[i][j]);
        }
        __syncthreads();
    }
#pragma unroll
    for (int i = 0; i < 4; i++) {
        float4 v = make_float4(acc[i][0], acc[i][1], acc[i][2], acc[i][3]);
        st(4 * ty + i, 4 * tx, v);
    }
}

// ---------------- the persistent RNN kernel ----------------
__global__ void __launch_bounds__(NT, 1) rnn_persistent_kernel(
    const int*   __restrict__ ids,     // [B,T]
    const float* __restrict__ emb,     // [V,E]
    const float* __restrict__ w_xh0,   // [H,E]
    const float* __restrict__ w_hh0,   // [H,H]
    const float* __restrict__ b_h0,    // [H]
    const float* __restrict__ w_xh1,   // [H,H]
    const float* __restrict__ w_hh1,   // [H,H]
    const float* __restrict__ b_h1,    // [H]
    const float* __restrict__ w_hy,    // [V,H]
    const float* __restrict__ b_y,     // [V]
    float* __restrict__ out,
    long long out_size)
{
    __shared__ float sA[32 * 68];
    __shared__ float sB[32 * 68];
    const int bid = blockIdx.x;
    const int tid = threadIdx.x;

    unsigned long long epoch = 0;
    if (tid == 0) epoch = g_epoch[bid];

    // ================= prologue =================
    // zero part0[parity 0] (needed at t=0) and g_h1 (h1_{-1} = 0)
    {
        float* z = &g_part0[0][0][0];   // 4 * B*H floats
        for (int i = tid; i < 4096; i += NT) z[bid * 4096 + i] = 0.f;
        for (int i = tid; i < 1024; i += NT) g_h1[bid * 1024 + i] = 0.f;
    }
    // tokproj[v][h] = b_h0[h] + sum_e emb[v][e] * w_xh0[h][e]
    {
        int mt = bid & 7;            // 8 m-tiles over V=512
        int nt = bid >> 3;           // 16 n-tiles over H=1024
        int m0 = mt * 64, n0 = nt * 64;
        gemm64(sA, sB, 0, EE,
            [&](int r, int k) { return emb[(m0 + r) * EE + k]; },
            [&](int r, int k) { return w_xh0[(n0 + r) * EE + k]; },
            [&](int m, int n, float4 v) {
                int col = n0 + n;
                float4 bb = *(const float4*)(b_h0 + col);
                v.x += bb.x; v.y += bb.y; v.z += bb.z; v.w += bb.w;
                *(float4*)(g_tokproj + (size_t)(m0 + m) * HH + col) = v;
            });
    }
    grid_bar(epoch);

    // ================= sequential loop =================
    for (int t = 0; t < TT; t++) {
        const int p = t & 1;
        const int q = p ^ 1;

        // ---- phase 1: GEMM A (pre0 partials) + finalize h1_{t-1} ----
        if (t > 0) {
            int mt = bid & 1;
            int nt = (bid >> 1) & 15;
            int kc = bid >> 5;
            int m0 = mt * 64, n0 = nt * 64;
            gemm64(sA, sB, kc * 256, kc * 256 + 256,
                [&](int r, int k) { return g_h0[(m0 + r) * HH + k]; },
                [&](int r, int k) { return w_hh0[(n0 + r) * HH + k]; },
                [&](int m, int n, float4 v) {
                    *(float4*)&g_part0[p][kc][(m0 + m) * HH + n0 + n] = v;
                });
            // h1_{t-1} = tanh(b_h1 + sum partials)  -> g_h1 (compact) + g_h1all[t-1]
            for (int i = tid; i < 1024; i += NT) {
                int idx = bid * 1024 + i;
                int k = idx & (HH - 1);
                float s = b_h1[k] + g_part1[q][0][idx] + g_part1[q][1][idx]
                                  + g_part1[q][2][idx] + g_part1[q][3][idx];
                float v = tanhf(s);
                g_h1[idx] = v;
                g_h1all[(size_t)(t - 1) * (BB * HH) + idx] = v;
            }
        }
        grid_bar(epoch);

        // ---- phase 2: GEMM B (pre1 partials) + finalize h0_t compact ----
        {
            int mt = bid & 1;
            int nt = (bid >> 1) & 15;
            int kc = bid >> 5;
            int m0 = mt * 64, n0 = nt * 64;
            int kbeg = kc * 512;
            auto stp = [&](int m, int n, float4 v) {
                *(float4*)&g_part1[p][kc][(m0 + m) * HH + n0 + n] = v;
            };
            if (kc < 2) {
                // first K-half: A = h0_t = tanh(tokproj[id] + sum part0[p])
                gemm64(sA, sB, kbeg, kbeg + 512,
                    [&](int r, int k) {
                        int b = m0 + r;
                        int id = ids[b * TT + t];
                        float s = g_tokproj[(size_t)id * HH + k]
                                + g_part0[p][0][b * HH + k] + g_part0[p][1][b * HH + k]
                                + g_part0[p][2][b * HH + k] + g_part0[p][3][b * HH + k];
                        return tanhf(s);
                    },
                    [&](int r, int k) { return w_xh1[(n0 + r) * HH + k]; },
                    stp);
            } else {
                // second K-half: A = h1_{t-1} (compact)
                gemm64(sA, sB, kbeg - 1024, kbeg - 1024 + 512,
                    [&](int r, int k) { return g_h1[(m0 + r) * HH + k]; },
                    [&](int r, int k) { return w_hh1[(n0 + r) * HH + k]; },
                    stp);
            }
            // compact h0_t for next step's GEMM A
            for (int i = tid; i < 1024; i += NT) {
                int idx = bid * 1024 + i;
                int b = idx >> 10;
                int k = idx & (HH - 1);
                int id = ids[b * TT + t];
                float s = g_tokproj[(size_t)id * HH + k]
                        + g_part0[p][0][idx] + g_part0[p][1][idx]
                        + g_part0[p][2][idx] + g_part0[p][3][idx];
                g_h0[idx] = tanhf(s);
            }
        }
        grid_bar(epoch);
    }

    // ================= epilogue =================
    // finalize h1_{T-1} (p=1 at t=1023), write final states if requested
    {
        const long long full = (long long)BB * TT * VV + 2LL * BB * HH;
        for (int i = tid; i < 1024; i += NT) {
            int idx = bid * 1024 + i;
            int k = idx & (HH - 1);
            float s = b_h1[k] + g_part1[1][0][idx] + g_part1[1][1][idx]
                              + g_part1[1][2][idx] + g_part1[1][3][idx];
            float v = tanhf(s);
            g_h1all[(size_t)(TT - 1) * (BB * HH) + idx] = v;
            if (out_size >= full) {
                out[(size_t)BB * TT * VV + idx] = g_h0[idx];            // h0 final
                out[(size_t)BB * TT * VV + BB * HH + idx] = v;           // h1 final
            }
        }
    }
    grid_bar(epoch);
    if (tid == 0) g_epoch[bid] = epoch;   // persist epoch for next replay

    // logits = h1all @ w_hy^T + b_y   (parallel GEMM, 16384 tiles of 64x64)
    for (int tile = bid; tile < 16384; tile += NB) {
        int mt = tile >> 3;            // 2048 m-tiles over B*T rows (layout [t][b])
        int nt = tile & 7;             // 8 n-tiles over V=512
        int m0 = mt * 64, n0 = nt * 64;
        gemm64(sA, sB, 0, HH,
            [&](int r, int k) { return g_h1all[(size_t)(m0 + r) * HH + k]; },
            [&](int r, int k) { return w_hy[(n0 + r) * HH + k]; },
            [&](int m, int n, float4 v) {
                int row = m0 + m;
                int tt = row >> 7;       // t
                int b  = row & 127;      // batch
                int col = n0 + n;
                float4 bb = *(const float4*)(b_y + col);
                v.x += bb.x; v.y += bb.y; v.z += bb.z; v.w += bb.w;
                *(float4*)&out[((size_t)b * TT + tt) * VV + col] = v;
            });
    }
}

// ---------------- launch ----------------
extern "C" void kernel_launch(void* const* d_in, const int* in_sizes, int n_in,
                              void* d_out, int out_size) {
    const int*   ids   = (const int*)d_in[0];
    const float* emb   = (const float*)d_in[1];
    const float* w_xh0 = (const float*)d_in[2];
    const float* w_hh0 = (const float*)d_in[3];
    const float* b_h0  = (const float*)d_in[4];
    const float* w_xh1 = (const float*)d_in[5];
    const float* w_hh1 = (const float*)d_in[6];
    const float* b_h1  = (const float*)d_in[7];
    const float* w_hy  = (const float*)d_in[8];
    const float* b_y   = (const float*)d_in[9];
    float* out = (float*)d_out;

    rnn_persistent_kernel<<<NB, NT>>>(ids, emb, w_xh0, w_hh0, b_h0,
                                      w_xh1, w_hh1, b_h1, w_hy, b_y,
                                      out, (long long)out_size);
}